// round 15
// baseline (speedup 1.0000x reference)
#include <cuda_runtime.h>
#include <cuda_fp16.h>
#include <math.h>
#include <stdint.h>

#define NE    32
#define KTOP  4
#define HDIM  1024
#define IDIM  512
#define TTOK  4096
#define CAP   1024

// ---------------- device scratch ----------------
__device__ int      g_count[NE];
__device__ int      g_tok[NE * CAP];
__device__ int      g_e4[TTOK * KTOP];
__device__ int      g_s4[TTOK * KTOP];
__device__ float    g_w4[TTOK * KTOP];
__device__ __half   g_xh[(size_t)TTOK * HDIM];            // fp16 x
__device__ __half   g_act[(size_t)NE * CAP * IDIM];       // fp16 silu(g)*u
__device__ __half   g_shact[(size_t)TTOK * IDIM];         // fp16 shared act
__device__ __half   g_dbuf[(size_t)NE * CAP * HDIM];      // fp16 down out
// fp16 k-pair-packed weights: u32[kp][n] = (half(W[2kp][n]), half(W[2kp+1][n]))
__device__ uint32_t g_wguh[(size_t)NE * (HDIM / 2) * (2 * IDIM)];  // 67 MB
__device__ uint32_t g_wdh[(size_t)NE * (IDIM / 2) * HDIM];         // 33.5 MB
__device__ uint32_t g_sguh[(HDIM / 2) * (2 * IDIM)];               // 2 MB
__device__ uint32_t g_sdh[(IDIM / 2) * HDIM];                      // 1 MB

// ---------------- helpers ----------------
__device__ __forceinline__ uint32_t pack2(float lo, float hi) {
    __half2 h = __floats2half2_rn(lo, hi);
    return *(uint32_t*)&h;
}
__device__ __forceinline__ void mma16(float* c, const uint32_t* a,
                                      uint32_t b0, uint32_t b1) {
    asm volatile(
        "mma.sync.aligned.m16n8k16.row.col.f32.f16.f16.f32 "
        "{%0,%1,%2,%3}, {%4,%5,%6,%7}, {%8,%9}, {%0,%1,%2,%3};"
        : "+f"(c[0]), "+f"(c[1]), "+f"(c[2]), "+f"(c[3])
        : "r"(a[0]), "r"(a[1]), "r"(a[2]), "r"(a[3]), "r"(b0), "r"(b1));
}
__device__ __forceinline__ void ldsm4(uint32_t* r, uint32_t saddr) {
    asm volatile("ldmatrix.sync.aligned.m8n8.x4.shared.b16 {%0,%1,%2,%3}, [%4];"
        : "=r"(r[0]), "=r"(r[1]), "=r"(r[2]), "=r"(r[3]) : "r"(saddr));
}
__device__ __forceinline__ uint32_t smem_u32(const void* p) {
    return (uint32_t)__cvta_generic_to_shared(p);
}
#define CP16(saddr, gptr) \
    asm volatile("cp.async.cg.shared.global [%0], [%1], 16;" \
        :: "r"(saddr), "l"(gptr) : "memory")
#define CP_COMMIT() asm volatile("cp.async.commit_group;" ::: "memory")
#define CP_WAIT1()  asm volatile("cp.async.wait_group 1;" ::: "memory")
#define CP_WAIT0()  asm volatile("cp.async.wait_group 0;" ::: "memory")

// ---------------- x -> fp16 ----------------
__global__ void __launch_bounds__(256)
cvt_x_kernel(const float* __restrict__ x) {
    const int i = blockIdx.x * 256 + threadIdx.x;
    const float4 v = ((const float4*)x)[i];
    __half2 h0 = __floats2half2_rn(v.x, v.y);
    __half2 h1 = __floats2half2_rn(v.z, v.w);
    ((uint2*)g_xh)[i] = make_uint2(*(uint32_t*)&h0, *(uint32_t*)&h1);
}

// ---------------- weight repack (dst resolved DEVICE-side) ----------------
// fp32 rows [2kp, 2kp+1] (1024 cols) -> u32 kp-packed row. which selects dst.
__global__ void __launch_bounds__(256)
repack_kernel(const float* __restrict__ src, int which) {
    uint32_t* dst = (which == 0) ? g_wguh :
                    (which == 1) ? g_wdh  :
                    (which == 2) ? g_sguh : g_sdh;
    const int kp = blockIdx.x, q = threadIdx.x;
    const float4 a = *(const float4*)(src + (size_t)(2 * kp) * 1024 + q * 4);
    const float4 b = *(const float4*)(src + (size_t)(2 * kp + 1) * 1024 + q * 4);
    uint4 u;
    u.x = pack2(a.x, b.x); u.y = pack2(a.y, b.y);
    u.z = pack2(a.z, b.z); u.w = pack2(a.w, b.w);
    ((uint4*)dst)[(size_t)kp * 256 + q] = u;
}

// ---------------- router ----------------
__global__ void zero_counts_kernel() {
    if (threadIdx.x < NE) g_count[threadIdx.x] = 0;
}

__global__ void router_kernel(const float* __restrict__ x,
                              const float* __restrict__ gw) {
    const int t = blockIdx.x;
    __shared__ float xs[HDIM];
    __shared__ float logits[NE];
    const float* xr = x + (size_t)t * HDIM;
    for (int i = threadIdx.x; i < HDIM; i += 128) xs[i] = xr[i];
    __syncthreads();

    const int warp = threadIdx.x >> 5, lane = threadIdx.x & 31;
    for (int i = 0; i < 8; i++) {
        const int e = warp * 8 + i;
        const float* w = gw + (size_t)e * HDIM;
        float s = 0.f;
        #pragma unroll 8
        for (int j = lane; j < HDIM; j += 32) s += xs[j] * w[j];
        #pragma unroll
        for (int o = 16; o > 0; o >>= 1) s += __shfl_down_sync(0xffffffffu, s, o);
        if (lane == 0) logits[e] = s;
    }
    __syncthreads();

    if (threadIdx.x == 0) {
        float mx = logits[0];
        #pragma unroll
        for (int e = 1; e < NE; e++) mx = fmaxf(mx, logits[e]);
        float p[NE];
        #pragma unroll
        for (int e = 0; e < NE; e++) p[e] = expf(logits[e] - mx);
        int idx[KTOP]; float pv[KTOP]; float psum = 0.f;
        bool used[NE];
        #pragma unroll
        for (int e = 0; e < NE; e++) used[e] = false;
        for (int k = 0; k < KTOP; k++) {
            float best = -1.f; int bi = 0;
            for (int e = 0; e < NE; e++)
                if (!used[e] && p[e] > best) { best = p[e]; bi = e; }
            used[bi] = true; idx[k] = bi; pv[k] = best; psum += best;
        }
        const float inv = 1.f / psum;
        for (int k = 0; k < KTOP; k++) {
            const int e = idx[k];
            const int pos = atomicAdd(&g_count[e], 1);
            if (pos < CAP) g_tok[e * CAP + pos] = t;
            g_e4[t * KTOP + k] = e;
            g_s4[t * KTOP + k] = pos;
            g_w4[t * KTOP + k] = pv[k] * inv;
        }
    }
}

// ---------------- GEMM layout ----------------
// A smem: 128 rows x 16 kp words, stride 20 (LDSM conflict-free).
// B smem: 16 kp x 128 n words, stride 136 (scalar frag LDS conflict-free).
#define ASZ 2560
#define BSZ 2176

// ---------------- gate-up (cp.async staged, fused silu, merged) -------------
// 128 thr, 4 warps (2M x 2N). block M=128, N=64 gate + 64 up. warp m64.
__global__ void __launch_bounds__(128)
gu_mma() {
    const int bid = blockIdx.x;
    const bool EXP = bid < 2048;
    int ez, my, nx;
    if (EXP) { ez = bid >> 6; my = (bid >> 3) & 7; nx = bid & 7; }
    else     { const int r = bid - 2048; ez = 0; my = r >> 3; nx = r & 7; }
    const int n_e = EXP ? min(g_count[ez], CAP) : TTOK;
    const int m0 = my * 128;
    if (m0 >= n_e) return;
    const int n0 = nx * 64;

    __shared__ uint32_t As_[2 * ASZ];
    __shared__ uint32_t Bs_[2 * BSZ];

    const int tid = threadIdx.x;
    const int wid = tid >> 5, lane = tid & 31;
    const int g = lane >> 2, tig = lane & 3;
    const int wm = wid & 1, wn = wid >> 1;

    const uint32_t* Wh = EXP ? g_wguh + (size_t)ez * (HDIM / 2) * (2 * IDIM) : g_sguh;
    __half* actb = EXP ? g_act + (size_t)ez * CAP * IDIM : g_shact;

    // A row per thread (invalid rows -> row 0; outputs never stored)
    const __half* arow;
    {
        const int r = m0 + tid;
        arow = g_xh + (size_t)((r < n_e) ? (EXP ? g_tok[ez * CAP + r] : r) : 0) * HDIM;
    }
    const int bq = lane;
    const int bcolu = (bq < 16) ? (n0 + bq * 4) : (IDIM + n0 + (bq - 16) * 4);

    float cg[4][4][4], cu[4][4][4];
    #pragma unroll
    for (int a = 0; a < 4; a++)
        #pragma unroll
        for (int b = 0; b < 4; b++)
            #pragma unroll
            for (int d = 0; d < 4; d++) { cg[a][b][d] = 0.f; cu[a][b][d] = 0.f; }

    const uint32_t As_bytes = smem_u32(As_);
    const uint32_t Bs_bytes = smem_u32(Bs_);
    const int lrow = (lane & 7) + ((lane >> 3) & 1) * 8;
    const int lcol = (lane >> 4) * 4;
    const uint32_t a_off = (uint32_t)(((wm * 64 + lrow) * 20 + lcol) * 4);
    const int bbase = tig * 136 + wn * 32 + g;

    // staging: A = 4x16B per thread; B = 4x16B (kp rows wid + i*4)
    #define GU_STAGE(bufi, k0) do { \
        const uint32_t sa = As_bytes + (bufi) * (ASZ * 4) + tid * 80; \
        const __half* ga = arow + (k0); \
        CP16(sa +  0, ga +  0); \
        CP16(sa + 16, ga +  8); \
        CP16(sa + 32, ga + 16); \
        CP16(sa + 48, ga + 24); \
        const int kpb = (k0) >> 1; \
        _Pragma("unroll") \
        for (int i = 0; i < 4; i++) { \
            const int kp = wid + i * 4; \
            CP16(Bs_bytes + (bufi) * (BSZ * 4) + (kp * 136 + bq * 4) * 4, \
                 Wh + (size_t)(kpb + kp) * (2 * IDIM) + bcolu); \
        } \
    } while (0)
    #define GU_COMP(kf) do { \
        uint32_t a[4][4]; \
        _Pragma("unroll") \
        for (int mf = 0; mf < 4; mf++) \
            ldsm4(a[mf], Aaddr + mf * 1280 + (kf) * 32); \
        _Pragma("unroll") \
        for (int nf = 0; nf < 4; nf++) { \
            const int ob = bbase + (kf) * 1088 + nf * 8; \
            const uint32_t bg0 = Bb[ob],      bg1 = Bb[ob + 544]; \
            const uint32_t bu0 = Bb[ob + 64], bu1 = Bb[ob + 608]; \
            _Pragma("unroll") \
            for (int mf = 0; mf < 4; mf++) { \
                mma16(cg[mf][nf], a[mf], bg0, bg1); \
                mma16(cu[mf][nf], a[mf], bu0, bu1); \
            } \
        } \
    } while (0)

    GU_STAGE(0, 0);
    CP_COMMIT();

    const int NC = HDIM / 32;
    for (int c = 0; c < NC; c++) {
        const int buf = c & 1;
        const uint32_t Aaddr = As_bytes + (uint32_t)buf * (ASZ * 4) + a_off;
        const uint32_t* Bb = Bs_ + buf * BSZ;
        if (c + 1 < NC) {
            GU_STAGE(buf ^ 1, (c + 1) * 32);
            CP_COMMIT();
            CP_WAIT1();
        } else {
            CP_WAIT0();
        }
        __syncthreads();
        GU_COMP(0);
        GU_COMP(1);
        __syncthreads();
    }
    #undef GU_STAGE
    #undef GU_COMP

    // epilogue: silu(gate)*up -> fp16 act
    #pragma unroll
    for (int mf = 0; mf < 4; mf++) {
        #pragma unroll
        for (int nf = 0; nf < 4; nf++) {
            const int row0 = m0 + wm * 64 + mf * 16 + g;
            const int col  = n0 + wn * 32 + nf * 8 + tig * 2;
            if (row0 < n_e) {
                float gv, uv, ox, oy;
                gv = cg[mf][nf][0]; uv = cu[mf][nf][0]; ox = gv / (1.f + __expf(-gv)) * uv;
                gv = cg[mf][nf][1]; uv = cu[mf][nf][1]; oy = gv / (1.f + __expf(-gv)) * uv;
                *(__half2*)(actb + (size_t)row0 * IDIM + col) = __floats2half2_rn(ox, oy);
            }
            if (row0 + 8 < n_e) {
                float gv, uv, ox, oy;
                gv = cg[mf][nf][2]; uv = cu[mf][nf][2]; ox = gv / (1.f + __expf(-gv)) * uv;
                gv = cg[mf][nf][3]; uv = cu[mf][nf][3]; oy = gv / (1.f + __expf(-gv)) * uv;
                *(__half2*)(actb + (size_t)(row0 + 8) * IDIM + col) = __floats2half2_rn(ox, oy);
            }
        }
    }
}

// ---------------- down (cp.async staged, merged) ----------------------------
// 128 thr, 4 warps (2M x 2N). block M=128 x N=128; warp m64 x n64.
__global__ void __launch_bounds__(128)
dn_mma(float* __restrict__ out) {
    const int bid = blockIdx.x;
    const bool EXP = bid < 2048;
    int ez, my, nx;
    if (EXP) { ez = bid >> 6; my = (bid >> 3) & 7; nx = bid & 7; }
    else     { const int r = bid - 2048; ez = 0; my = r >> 3; nx = r & 7; }
    const int n_e = EXP ? min(g_count[ez], CAP) : TTOK;
    const int m0 = my * 128;
    if (m0 >= n_e) return;
    const int n0 = nx * 128;

    __shared__ uint32_t As_[2 * ASZ];
    __shared__ uint32_t Bs_[2 * BSZ];

    const int tid = threadIdx.x;
    const int wid = tid >> 5, lane = tid & 31;
    const int g = lane >> 2, tig = lane & 3;
    const int wm = wid & 1, wn = wid >> 1;

    const __half* actb = EXP ? g_act + (size_t)ez * CAP * IDIM : g_shact;
    const uint32_t* Wh = EXP ? g_wdh + (size_t)ez * (IDIM / 2) * HDIM : g_sdh;

    const __half* arow = actb + (size_t)(m0 + tid) * IDIM;
    const int bq = lane;
    const int bcolu = n0 + bq * 4;

    float cc[4][8][4];
    #pragma unroll
    for (int a = 0; a < 4; a++)
        #pragma unroll
        for (int b = 0; b < 8; b++)
            #pragma unroll
            for (int d = 0; d < 4; d++) cc[a][b][d] = 0.f;

    const uint32_t As_bytes = smem_u32(As_);
    const uint32_t Bs_bytes = smem_u32(Bs_);
    const int lrow = (lane & 7) + ((lane >> 3) & 1) * 8;
    const int lcol = (lane >> 4) * 4;
    const uint32_t a_off = (uint32_t)(((wm * 64 + lrow) * 20 + lcol) * 4);
    const int bbase = tig * 136 + wn * 64 + g;

    #define DN_STAGE(bufi, k0) do { \
        const uint32_t sa = As_bytes + (bufi) * (ASZ * 4) + tid * 80; \
        const __half* ga = arow + (k0); \
        CP16(sa +  0, ga +  0); \
        CP16(sa + 16, ga +  8); \
        CP16(sa + 32, ga + 16); \
        CP16(sa + 48, ga + 24); \
        const int kpb = (k0) >> 1; \
        _Pragma("unroll") \
        for (int i = 0; i < 4; i++) { \
            const int kp = wid + i * 4; \
            CP16(Bs_bytes + (bufi) * (BSZ * 4) + (kp * 136 + bq * 4) * 4, \
                 Wh + (size_t)(kpb + kp) * HDIM + bcolu); \
        } \
    } while (0)
    #define DN_COMP(kf) do { \
        uint32_t a[4][4]; \
        _Pragma("unroll") \
        for (int mf = 0; mf < 4; mf++) \
            ldsm4(a[mf], Aaddr + mf * 1280 + (kf) * 32); \
        _Pragma("unroll") \
        for (int nf = 0; nf < 8; nf++) { \
            const int ob = bbase + (kf) * 1088 + nf * 8; \
            const uint32_t b0 = Bb[ob], b1 = Bb[ob + 544]; \
            _Pragma("unroll") \
            for (int mf = 0; mf < 4; mf++) \
                mma16(cc[mf][nf], a[mf], b0, b1); \
        } \
    } while (0)

    DN_STAGE(0, 0);
    CP_COMMIT();

    const int NC = IDIM / 32;
    for (int c = 0; c < NC; c++) {
        const int buf = c & 1;
        const uint32_t Aaddr = As_bytes + (uint32_t)buf * (ASZ * 4) + a_off;
        const uint32_t* Bb = Bs_ + buf * BSZ;
        if (c + 1 < NC) {
            DN_STAGE(buf ^ 1, (c + 1) * 32);
            CP_COMMIT();
            CP_WAIT1();
        } else {
            CP_WAIT0();
        }
        __syncthreads();
        DN_COMP(0);
        DN_COMP(1);
        __syncthreads();
    }
    #undef DN_STAGE
    #undef DN_COMP

    #pragma unroll
    for (int mf = 0; mf < 4; mf++) {
        #pragma unroll
        for (int nf = 0; nf < 8; nf++) {
            const int row0 = m0 + wm * 64 + mf * 16 + g;
            const int col  = n0 + wn * 64 + nf * 8 + tig * 2;
            if (row0 < n_e) {
                if (EXP) {
                    *(__half2*)(g_dbuf + ((size_t)ez * CAP + row0) * HDIM + col) =
                        __floats2half2_rn(cc[mf][nf][0], cc[mf][nf][1]);
                } else {
                    *(float2*)(out + (size_t)row0 * HDIM + col) =
                        make_float2(cc[mf][nf][0], cc[mf][nf][1]);
                }
            }
            if (row0 + 8 < n_e) {
                if (EXP) {
                    *(__half2*)(g_dbuf + ((size_t)ez * CAP + row0 + 8) * HDIM + col) =
                        __floats2half2_rn(cc[mf][nf][2], cc[mf][nf][3]);
                } else {
                    *(float2*)(out + (size_t)(row0 + 8) * HDIM + col) =
                        make_float2(cc[mf][nf][2], cc[mf][nf][3]);
                }
            }
        }
    }
}

// ---------------- combine ----------------
__global__ void __launch_bounds__(128)
combine_kernel(float* __restrict__ out) {
    const int t = blockIdx.x;
    const int i = threadIdx.x;
    float4* outv = (float4*)out + (size_t)t * 256 + i * 2;
    float4 a0 = outv[0], a1 = outv[1];
    #pragma unroll
    for (int k = 0; k < KTOP; k++) {
        const int e = g_e4[t * KTOP + k];
        const int s = g_s4[t * KTOP + k];
        const float w = g_w4[t * KTOP + k];
        if (s < CAP) {
            const uint4 hv = *(const uint4*)(g_dbuf + ((size_t)e * CAP + s) * HDIM + i * 8);
            const float2 f0 = __half22float2(*(const __half2*)&hv.x);
            const float2 f1 = __half22float2(*(const __half2*)&hv.y);
            const float2 f2 = __half22float2(*(const __half2*)&hv.z);
            const float2 f3 = __half22float2(*(const __half2*)&hv.w);
            a0.x += w * f0.x; a0.y += w * f0.y; a0.z += w * f1.x; a0.w += w * f1.y;
            a1.x += w * f2.x; a1.y += w * f2.y; a1.z += w * f3.x; a1.w += w * f3.y;
        }
    }
    outv[0] = a0; outv[1] = a1;
}

extern "C" void kernel_launch(void* const* d_in, const int* in_sizes, int n_in,
                              void* d_out, int out_size) {
    const float* x   = (const float*)d_in[0];
    const float* gw  = (const float*)d_in[1];
    const float* wgu = (const float*)d_in[2];
    const float* wd  = (const float*)d_in[3];
    const float* sgu = (const float*)d_in[4];
    const float* sd  = (const float*)d_in[5];
    float* out = (float*)d_out;
    (void)in_sizes; (void)n_in; (void)out_size;

    zero_counts_kernel<<<1, 32>>>();
    cvt_x_kernel<<<(TTOK * HDIM) / 1024, 256>>>(x);
    router_kernel<<<TTOK, 128>>>(x, gw);

    // weight repacks (dst selected device-side: 0=wgu 1=wd 2=sgu 3=sd)
    repack_kernel<<<NE * HDIM / 2, 256>>>(wgu, 0);
    repack_kernel<<<NE * IDIM / 2, 256>>>(wd,  1);
    repack_kernel<<<HDIM / 2, 256>>>(sgu, 2);
    repack_kernel<<<IDIM / 2, 256>>>(sd,  3);

    gu_mma<<<2304, 128>>>();
    dn_mma<<<2304, 128>>>(out);

    combine_kernel<<<TTOK, 128>>>(out);
}

// round 16
// speedup vs baseline: 1.3230x; 1.3230x over previous
#include <cuda_runtime.h>
#include <cuda_fp16.h>
#include <math.h>
#include <stdint.h>

#define NE    32
#define KTOP  4
#define HDIM  1024
#define IDIM  512
#define TTOK  4096
#define CAP   1024

// ---------------- device scratch ----------------
__device__ int      g_count[NE];
__device__ int      g_tok[NE * CAP];
__device__ int      g_e4[TTOK * KTOP];
__device__ int      g_s4[TTOK * KTOP];
__device__ float    g_w4[TTOK * KTOP];
__device__ __half   g_xh[(size_t)TTOK * HDIM];            // fp16 x (router writes)
__device__ __half   g_act[(size_t)NE * CAP * IDIM];       // fp16 silu(g)*u
__device__ __half   g_shact[(size_t)TTOK * IDIM];         // fp16 shared act
__device__ __half   g_dbuf[(size_t)NE * CAP * HDIM];      // fp16 down out
// fp16 k-pair-packed weights: u32[kp][n] = (half(W[2kp][n]), half(W[2kp+1][n]))
__device__ uint32_t g_wguh[(size_t)NE * (HDIM / 2) * (2 * IDIM)];  // 67 MB
__device__ uint32_t g_wdh[(size_t)NE * (IDIM / 2) * HDIM];         // 33.5 MB
__device__ uint32_t g_sguh[(HDIM / 2) * (2 * IDIM)];               // 2 MB
__device__ uint32_t g_sdh[(IDIM / 2) * HDIM];                      // 1 MB

// ---------------- helpers ----------------
__device__ __forceinline__ uint32_t pack2(float lo, float hi) {
    __half2 h = __floats2half2_rn(lo, hi);
    return *(uint32_t*)&h;
}
__device__ __forceinline__ void mma16(float* c, const uint32_t* a,
                                      uint32_t b0, uint32_t b1) {
    asm volatile(
        "mma.sync.aligned.m16n8k16.row.col.f32.f16.f16.f32 "
        "{%0,%1,%2,%3}, {%4,%5,%6,%7}, {%8,%9}, {%0,%1,%2,%3};"
        : "+f"(c[0]), "+f"(c[1]), "+f"(c[2]), "+f"(c[3])
        : "r"(a[0]), "r"(a[1]), "r"(a[2]), "r"(a[3]), "r"(b0), "r"(b1));
}
__device__ __forceinline__ void ldsm4(uint32_t* r, uint32_t saddr) {
    asm volatile("ldmatrix.sync.aligned.m8n8.x4.shared.b16 {%0,%1,%2,%3}, [%4];"
        : "=r"(r[0]), "=r"(r[1]), "=r"(r[2]), "=r"(r[3]) : "r"(saddr));
}
__device__ __forceinline__ uint32_t smem_u32(const void* p) {
    return (uint32_t)__cvta_generic_to_shared(p);
}

// ---------------- weight repack (dst resolved DEVICE-side) ----------------
__global__ void __launch_bounds__(256)
repack_kernel(const float* __restrict__ src, int which) {
    uint32_t* dst = (which == 0) ? g_wguh :
                    (which == 1) ? g_wdh  :
                    (which == 2) ? g_sguh : g_sdh;
    const int kp = blockIdx.x, q = threadIdx.x;
    const float4 a = *(const float4*)(src + (size_t)(2 * kp) * 1024 + q * 4);
    const float4 b = *(const float4*)(src + (size_t)(2 * kp + 1) * 1024 + q * 4);
    uint4 u;
    u.x = pack2(a.x, b.x); u.y = pack2(a.y, b.y);
    u.z = pack2(a.z, b.z); u.w = pack2(a.w, b.w);
    ((uint4*)dst)[(size_t)kp * 256 + q] = u;
}

// ---------------- router (also emits fp16 x) ----------------
__global__ void zero_counts_kernel() {
    if (threadIdx.x < NE) g_count[threadIdx.x] = 0;
}

__global__ void router_kernel(const float* __restrict__ x,
                              const float* __restrict__ gw) {
    const int t = blockIdx.x;
    __shared__ float xs[HDIM];
    __shared__ float logits[NE];
    const float* xr = x + (size_t)t * HDIM;
    for (int i = threadIdx.x; i < HDIM; i += 128) xs[i] = xr[i];
    __syncthreads();

    // fold in x -> fp16 conversion
    for (int i = threadIdx.x; i < HDIM / 2; i += 128)
        ((__half2*)g_xh)[(size_t)t * (HDIM / 2) + i] =
            __floats2half2_rn(xs[2 * i], xs[2 * i + 1]);

    const int warp = threadIdx.x >> 5, lane = threadIdx.x & 31;
    for (int i = 0; i < 8; i++) {
        const int e = warp * 8 + i;
        const float* w = gw + (size_t)e * HDIM;
        float s = 0.f;
        #pragma unroll 8
        for (int j = lane; j < HDIM; j += 32) s += xs[j] * w[j];
        #pragma unroll
        for (int o = 16; o > 0; o >>= 1) s += __shfl_down_sync(0xffffffffu, s, o);
        if (lane == 0) logits[e] = s;
    }
    __syncthreads();

    if (threadIdx.x == 0) {
        float mx = logits[0];
        #pragma unroll
        for (int e = 1; e < NE; e++) mx = fmaxf(mx, logits[e]);
        float p[NE];
        #pragma unroll
        for (int e = 0; e < NE; e++) p[e] = expf(logits[e] - mx);
        int idx[KTOP]; float pv[KTOP]; float psum = 0.f;
        bool used[NE];
        #pragma unroll
        for (int e = 0; e < NE; e++) used[e] = false;
        for (int k = 0; k < KTOP; k++) {
            float best = -1.f; int bi = 0;
            for (int e = 0; e < NE; e++)
                if (!used[e] && p[e] > best) { best = p[e]; bi = e; }
            used[bi] = true; idx[k] = bi; pv[k] = best; psum += best;
        }
        const float inv = 1.f / psum;
        for (int k = 0; k < KTOP; k++) {
            const int e = idx[k];
            const int pos = atomicAdd(&g_count[e], 1);
            if (pos < CAP) g_tok[e * CAP + pos] = t;
            g_e4[t * KTOP + k] = e;
            g_s4[t * KTOP + k] = pos;
            g_w4[t * KTOP + k] = pv[k] * inv;
        }
    }
}

// ---------------- GEMM layout ----------------
// A smem: 128 rows x 16 kp words, stride 20 (LDSM conflict-free).
// B smem: 16 kp x 128 n words, stride 136 (scalar frag LDS conflict-free).
#define ASZ 2560
#define BSZ 2176

// ---------------- gate-up (register-staged, packed fp16 B, fused silu) ------
// 128 thr, 4 warps (2M x 2N). block M=128, N=64 gate + 64 up. warp m64.
__global__ void __launch_bounds__(128)
gu_mma() {
    const int bid = blockIdx.x;
    const bool EXP = bid < 2048;
    int ez, my, nx;
    if (EXP) { ez = bid >> 6; my = (bid >> 3) & 7; nx = bid & 7; }
    else     { const int r = bid - 2048; ez = 0; my = r >> 3; nx = r & 7; }
    const int n_e = EXP ? min(g_count[ez], CAP) : TTOK;
    const int m0 = my * 128;
    if (m0 >= n_e) return;
    const int n0 = nx * 64;

    __shared__ uint32_t As_[2 * ASZ];
    __shared__ uint32_t Bs_[2 * BSZ];

    const int tid = threadIdx.x;
    const int wid = tid >> 5, lane = tid & 31;
    const int g = lane >> 2, tig = lane & 3;
    const int wm = wid & 1, wn = wid >> 1;

    const uint32_t* Wh = EXP ? g_wguh + (size_t)ez * (HDIM / 2) * (2 * IDIM) : g_sguh;
    __half* actb = EXP ? g_act + (size_t)ez * CAP * IDIM : g_shact;

    const __half* arow;
    {
        const int r = m0 + tid;
        arow = g_xh + (size_t)((r < n_e) ? (EXP ? g_tok[ez * CAP + r] : r) : 0) * HDIM;
    }
    const int bk = wid, bq = lane;
    // packed u32 col index: gate n -> n, up n -> 512 + n
    const int bcolu = (bq < 16) ? (n0 + bq * 4) : (IDIM + n0 + (bq - 16) * 4);

    float cg[4][4][4], cu[4][4][4];
    #pragma unroll
    for (int a = 0; a < 4; a++)
        #pragma unroll
        for (int b = 0; b < 4; b++)
            #pragma unroll
            for (int d = 0; d < 4; d++) { cg[a][b][d] = 0.f; cu[a][b][d] = 0.f; }

    const uint32_t As_bytes = smem_u32(As_);
    const int lrow = (lane & 7) + ((lane >> 3) & 1) * 8;
    const int lcol = (lane >> 4) * 4;
    const uint32_t a_off = (uint32_t)(((wm * 64 + lrow) * 20 + lcol) * 4);
    const int bbase = tig * 136 + wn * 32 + g;

    uint4 ra16[2], rb16[2];
    // half h: A k [h*16, h*16+16); B kp rows {bk + (2h)*4, bk + (2h+1)*4}
    #define GU_LDGA(k0, h) do { \
        ra16[0] = *(const uint4*)(arow + (k0) + (h) * 16); \
        ra16[1] = *(const uint4*)(arow + (k0) + (h) * 16 + 8); \
    } while (0)
    #define GU_LDGB(k0, h) do { \
        _Pragma("unroll") \
        for (int q2 = 0; q2 < 2; q2++) { \
            const int kp = bk + ((h) * 2 + q2) * 4; \
            rb16[q2] = *(const uint4*)(Wh + (size_t)(((k0) >> 1) + kp) * 1024 + bcolu); \
        } \
    } while (0)
    #define GU_STS(bufi, h) do { \
        *(uint4*)&As_[(bufi) * ASZ + tid * 20 + (h) * 8 + 0] = ra16[0]; \
        *(uint4*)&As_[(bufi) * ASZ + tid * 20 + (h) * 8 + 4] = ra16[1]; \
        _Pragma("unroll") \
        for (int q2 = 0; q2 < 2; q2++) { \
            const int kp = bk + ((h) * 2 + q2) * 4; \
            *(uint4*)&Bs_[(bufi) * BSZ + kp * 136 + bq * 4] = rb16[q2]; \
        } \
    } while (0)
    #define GU_COMP(kf) do { \
        uint32_t a[4][4]; \
        _Pragma("unroll") \
        for (int mf = 0; mf < 4; mf++) \
            ldsm4(a[mf], Aaddr + mf * 1280 + (kf) * 32); \
        _Pragma("unroll") \
        for (int nf = 0; nf < 4; nf++) { \
            const int ob = bbase + (kf) * 1088 + nf * 8; \
            const uint32_t bg0 = Bb[ob],      bg1 = Bb[ob + 544]; \
            const uint32_t bu0 = Bb[ob + 64], bu1 = Bb[ob + 608]; \
            _Pragma("unroll") \
            for (int mf = 0; mf < 4; mf++) { \
                mma16(cg[mf][nf], a[mf], bg0, bg1); \
                mma16(cu[mf][nf], a[mf], bu0, bu1); \
            } \
        } \
    } while (0)

    GU_LDGA(0, 0);  GU_LDGB(0, 0);  GU_STS(0, 0);
    GU_LDGA(0, 1);  GU_LDGB(0, 1);  GU_STS(0, 1);
    __syncthreads();

    const int NC = HDIM / 32;
    for (int c = 0; c < NC; c++) {
        const int buf = c & 1;
        const uint32_t Aaddr = As_bytes + (uint32_t)buf * (ASZ * 4) + a_off;
        const uint32_t* Bb = Bs_ + buf * BSZ;
        const bool more = (c + 1 < NC);
        if (more) { GU_LDGA((c + 1) * 32, 0); GU_LDGB((c + 1) * 32, 0); }
        GU_COMP(0);
        if (more) { GU_STS(buf ^ 1, 0); GU_LDGA((c + 1) * 32, 1); GU_LDGB((c + 1) * 32, 1); }
        GU_COMP(1);
        if (more) { GU_STS(buf ^ 1, 1); }
        __syncthreads();
    }
    #undef GU_LDGA
    #undef GU_LDGB
    #undef GU_STS
    #undef GU_COMP

    // epilogue: silu(gate)*up -> fp16 act
    #pragma unroll
    for (int mf = 0; mf < 4; mf++) {
        #pragma unroll
        for (int nf = 0; nf < 4; nf++) {
            const int row0 = m0 + wm * 64 + mf * 16 + g;
            const int col  = n0 + wn * 32 + nf * 8 + tig * 2;
            if (row0 < n_e) {
                float gv, uv, ox, oy;
                gv = cg[mf][nf][0]; uv = cu[mf][nf][0]; ox = gv / (1.f + __expf(-gv)) * uv;
                gv = cg[mf][nf][1]; uv = cu[mf][nf][1]; oy = gv / (1.f + __expf(-gv)) * uv;
                *(__half2*)(actb + (size_t)row0 * IDIM + col) = __floats2half2_rn(ox, oy);
            }
            if (row0 + 8 < n_e) {
                float gv, uv, ox, oy;
                gv = cg[mf][nf][2]; uv = cu[mf][nf][2]; ox = gv / (1.f + __expf(-gv)) * uv;
                gv = cg[mf][nf][3]; uv = cu[mf][nf][3]; oy = gv / (1.f + __expf(-gv)) * uv;
                *(__half2*)(actb + (size_t)(row0 + 8) * IDIM + col) = __floats2half2_rn(ox, oy);
            }
        }
    }
}

// ---------------- down (register-staged, packed fp16 B, merged) -------------
// 128 thr, 4 warps (2M x 2N). block M=128 x N=128; warp m64 x n64.
__global__ void __launch_bounds__(128)
dn_mma(float* __restrict__ out) {
    const int bid = blockIdx.x;
    const bool EXP = bid < 2048;
    int ez, my, nx;
    if (EXP) { ez = bid >> 6; my = (bid >> 3) & 7; nx = bid & 7; }
    else     { const int r = bid - 2048; ez = 0; my = r >> 3; nx = r & 7; }
    const int n_e = EXP ? min(g_count[ez], CAP) : TTOK;
    const int m0 = my * 128;
    if (m0 >= n_e) return;
    const int n0 = nx * 128;

    __shared__ uint32_t As_[2 * ASZ];
    __shared__ uint32_t Bs_[2 * BSZ];

    const int tid = threadIdx.x;
    const int wid = tid >> 5, lane = tid & 31;
    const int g = lane >> 2, tig = lane & 3;
    const int wm = wid & 1, wn = wid >> 1;

    const __half* actb = EXP ? g_act + (size_t)ez * CAP * IDIM : g_shact;
    const uint32_t* Wh = EXP ? g_wdh + (size_t)ez * (IDIM / 2) * HDIM : g_sdh;

    const __half* arow = actb + (size_t)(m0 + tid) * IDIM;
    const int bk = wid, bq = lane;
    const int bcolu = n0 + bq * 4;

    float cc[4][8][4];
    #pragma unroll
    for (int a = 0; a < 4; a++)
        #pragma unroll
        for (int b = 0; b < 8; b++)
            #pragma unroll
            for (int d = 0; d < 4; d++) cc[a][b][d] = 0.f;

    const uint32_t As_bytes = smem_u32(As_);
    const int lrow = (lane & 7) + ((lane >> 3) & 1) * 8;
    const int lcol = (lane >> 4) * 4;
    const uint32_t a_off = (uint32_t)(((wm * 64 + lrow) * 20 + lcol) * 4);
    const int bbase = tig * 136 + wn * 64 + g;

    uint4 ra16[2], rb16[2];
    #define DN_LDGA(k0, h) do { \
        ra16[0] = *(const uint4*)(arow + (k0) + (h) * 16); \
        ra16[1] = *(const uint4*)(arow + (k0) + (h) * 16 + 8); \
    } while (0)
    #define DN_LDGB(k0, h) do { \
        _Pragma("unroll") \
        for (int q2 = 0; q2 < 2; q2++) { \
            const int kp = bk + ((h) * 2 + q2) * 4; \
            rb16[q2] = *(const uint4*)(Wh + (size_t)(((k0) >> 1) + kp) * 1024 + bcolu); \
        } \
    } while (0)
    #define DN_STS(bufi, h) do { \
        *(uint4*)&As_[(bufi) * ASZ + tid * 20 + (h) * 8 + 0] = ra16[0]; \
        *(uint4*)&As_[(bufi) * ASZ + tid * 20 + (h) * 8 + 4] = ra16[1]; \
        _Pragma("unroll") \
        for (int q2 = 0; q2 < 2; q2++) { \
            const int kp = bk + ((h) * 2 + q2) * 4; \
            *(uint4*)&Bs_[(bufi) * BSZ + kp * 136 + bq * 4] = rb16[q2]; \
        } \
    } while (0)
    #define DN_COMP(kf) do { \
        uint32_t a[4][4]; \
        _Pragma("unroll") \
        for (int mf = 0; mf < 4; mf++) \
            ldsm4(a[mf], Aaddr + mf * 1280 + (kf) * 32); \
        _Pragma("unroll") \
        for (int nf = 0; nf < 8; nf++) { \
            const int ob = bbase + (kf) * 1088 + nf * 8; \
            const uint32_t b0 = Bb[ob], b1 = Bb[ob + 544]; \
            _Pragma("unroll") \
            for (int mf = 0; mf < 4; mf++) \
                mma16(cc[mf][nf], a[mf], b0, b1); \
        } \
    } while (0)

    DN_LDGA(0, 0);  DN_LDGB(0, 0);  DN_STS(0, 0);
    DN_LDGA(0, 1);  DN_LDGB(0, 1);  DN_STS(0, 1);
    __syncthreads();

    const int NC = IDIM / 32;
    for (int c = 0; c < NC; c++) {
        const int buf = c & 1;
        const uint32_t Aaddr = As_bytes + (uint32_t)buf * (ASZ * 4) + a_off;
        const uint32_t* Bb = Bs_ + buf * BSZ;
        const bool more = (c + 1 < NC);
        if (more) { DN_LDGA((c + 1) * 32, 0); DN_LDGB((c + 1) * 32, 0); }
        DN_COMP(0);
        if (more) { DN_STS(buf ^ 1, 0); DN_LDGA((c + 1) * 32, 1); DN_LDGB((c + 1) * 32, 1); }
        DN_COMP(1);
        if (more) { DN_STS(buf ^ 1, 1); }
        __syncthreads();
    }
    #undef DN_LDGA
    #undef DN_LDGB
    #undef DN_STS
    #undef DN_COMP

    #pragma unroll
    for (int mf = 0; mf < 4; mf++) {
        #pragma unroll
        for (int nf = 0; nf < 8; nf++) {
            const int row0 = m0 + wm * 64 + mf * 16 + g;
            const int col  = n0 + wn * 64 + nf * 8 + tig * 2;
            if (row0 < n_e) {
                if (EXP) {
                    *(__half2*)(g_dbuf + ((size_t)ez * CAP + row0) * HDIM + col) =
                        __floats2half2_rn(cc[mf][nf][0], cc[mf][nf][1]);
                } else {
                    *(float2*)(out + (size_t)row0 * HDIM + col) =
                        make_float2(cc[mf][nf][0], cc[mf][nf][1]);
                }
            }
            if (row0 + 8 < n_e) {
                if (EXP) {
                    *(__half2*)(g_dbuf + ((size_t)ez * CAP + row0 + 8) * HDIM + col) =
                        __floats2half2_rn(cc[mf][nf][2], cc[mf][nf][3]);
                } else {
                    *(float2*)(out + (size_t)(row0 + 8) * HDIM + col) =
                        make_float2(cc[mf][nf][2], cc[mf][nf][3]);
                }
            }
        }
    }
}

// ---------------- combine ----------------
__global__ void __launch_bounds__(128)
combine_kernel(float* __restrict__ out) {
    const int t = blockIdx.x;
    const int i = threadIdx.x;
    float4* outv = (float4*)out + (size_t)t * 256 + i * 2;
    float4 a0 = outv[0], a1 = outv[1];
    #pragma unroll
    for (int k = 0; k < KTOP; k++) {
        const int e = g_e4[t * KTOP + k];
        const int s = g_s4[t * KTOP + k];
        const float w = g_w4[t * KTOP + k];
        if (s < CAP) {
            const uint4 hv = *(const uint4*)(g_dbuf + ((size_t)e * CAP + s) * HDIM + i * 8);
            const float2 f0 = __half22float2(*(const __half2*)&hv.x);
            const float2 f1 = __half22float2(*(const __half2*)&hv.y);
            const float2 f2 = __half22float2(*(const __half2*)&hv.z);
            const float2 f3 = __half22float2(*(const __half2*)&hv.w);
            a0.x += w * f0.x; a0.y += w * f0.y; a0.z += w * f1.x; a0.w += w * f1.y;
            a1.x += w * f2.x; a1.y += w * f2.y; a1.z += w * f3.x; a1.w += w * f3.y;
        }
    }
    outv[0] = a0; outv[1] = a1;
}

extern "C" void kernel_launch(void* const* d_in, const int* in_sizes, int n_in,
                              void* d_out, int out_size) {
    const float* x   = (const float*)d_in[0];
    const float* gw  = (const float*)d_in[1];
    const float* wgu = (const float*)d_in[2];
    const float* wd  = (const float*)d_in[3];
    const float* sgu = (const float*)d_in[4];
    const float* sd  = (const float*)d_in[5];
    float* out = (float*)d_out;
    (void)in_sizes; (void)n_in; (void)out_size;

    zero_counts_kernel<<<1, 32>>>();
    router_kernel<<<TTOK, 128>>>(x, gw);   // also writes g_xh (fp16 x)

    // weight repacks (dst selected device-side: 0=wgu 1=wd 2=sgu 3=sd)
    repack_kernel<<<NE * HDIM / 2, 256>>>(wgu, 0);
    repack_kernel<<<NE * IDIM / 2, 256>>>(wd,  1);
    repack_kernel<<<HDIM / 2, 256>>>(sgu, 2);
    repack_kernel<<<IDIM / 2, 256>>>(sd,  3);

    gu_mma<<<2304, 128>>>();
    dn_mma<<<2304, 128>>>(out);

    combine_kernel<<<TTOK, 128>>>(out);
}

// round 17
// speedup vs baseline: 1.3895x; 1.0503x over previous
#include <cuda_runtime.h>
#include <cuda_fp16.h>
#include <math.h>
#include <stdint.h>

#define NE    32
#define KTOP  4
#define HDIM  1024
#define IDIM  512
#define TTOK  4096
#define CAP   1024

// ---------------- device scratch ----------------
__device__ int      g_count[NE];
__device__ int      g_tok[NE * CAP];
__device__ int      g_e4[TTOK * KTOP];
__device__ int      g_s4[TTOK * KTOP];
__device__ float    g_w4[TTOK * KTOP];
__device__ __half   g_xh[(size_t)TTOK * HDIM];            // fp16 x (router writes)
__device__ __half   g_act[(size_t)NE * CAP * IDIM];       // fp16 silu(g)*u
__device__ __half   g_shact[(size_t)TTOK * IDIM];         // fp16 shared act
__device__ __half   g_dbuf[(size_t)NE * CAP * HDIM];      // fp16 down out

// ---------------- helpers ----------------
__device__ __forceinline__ uint32_t pack2(float lo, float hi) {
    __half2 h = __floats2half2_rn(lo, hi);
    return *(uint32_t*)&h;
}
__device__ __forceinline__ void mma16(float* c, const uint32_t* a,
                                      uint32_t b0, uint32_t b1) {
    asm volatile(
        "mma.sync.aligned.m16n8k16.row.col.f32.f16.f16.f32 "
        "{%0,%1,%2,%3}, {%4,%5,%6,%7}, {%8,%9}, {%0,%1,%2,%3};"
        : "+f"(c[0]), "+f"(c[1]), "+f"(c[2]), "+f"(c[3])
        : "r"(a[0]), "r"(a[1]), "r"(a[2]), "r"(a[3]), "r"(b0), "r"(b1));
}
__device__ __forceinline__ void ldsm4(uint32_t* r, uint32_t saddr) {
    asm volatile("ldmatrix.sync.aligned.m8n8.x4.shared.b16 {%0,%1,%2,%3}, [%4];"
        : "=r"(r[0]), "=r"(r[1]), "=r"(r[2]), "=r"(r[3]) : "r"(saddr));
}
__device__ __forceinline__ uint32_t smem_u32(const void* p) {
    return (uint32_t)__cvta_generic_to_shared(p);
}

// ---------------- router (also emits fp16 x) ----------------
__global__ void zero_counts_kernel() {
    if (threadIdx.x < NE) g_count[threadIdx.x] = 0;
}

__global__ void router_kernel(const float* __restrict__ x,
                              const float* __restrict__ gw) {
    const int t = blockIdx.x;
    __shared__ float xs[HDIM];
    __shared__ float logits[NE];
    const float* xr = x + (size_t)t * HDIM;
    for (int i = threadIdx.x; i < HDIM; i += 128) xs[i] = xr[i];
    __syncthreads();

    // folded x -> fp16 conversion (xs already resident)
    for (int i = threadIdx.x; i < HDIM / 2; i += 128)
        ((__half2*)g_xh)[(size_t)t * (HDIM / 2) + i] =
            __floats2half2_rn(xs[2 * i], xs[2 * i + 1]);

    const int warp = threadIdx.x >> 5, lane = threadIdx.x & 31;
    for (int i = 0; i < 8; i++) {
        const int e = warp * 8 + i;
        const float* w = gw + (size_t)e * HDIM;
        float s = 0.f;
        #pragma unroll 8
        for (int j = lane; j < HDIM; j += 32) s += xs[j] * w[j];
        #pragma unroll
        for (int o = 16; o > 0; o >>= 1) s += __shfl_down_sync(0xffffffffu, s, o);
        if (lane == 0) logits[e] = s;
    }
    __syncthreads();

    if (threadIdx.x == 0) {
        float mx = logits[0];
        #pragma unroll
        for (int e = 1; e < NE; e++) mx = fmaxf(mx, logits[e]);
        float p[NE];
        #pragma unroll
        for (int e = 0; e < NE; e++) p[e] = expf(logits[e] - mx);
        int idx[KTOP]; float pv[KTOP]; float psum = 0.f;
        bool used[NE];
        #pragma unroll
        for (int e = 0; e < NE; e++) used[e] = false;
        for (int k = 0; k < KTOP; k++) {
            float best = -1.f; int bi = 0;
            for (int e = 0; e < NE; e++)
                if (!used[e] && p[e] > best) { best = p[e]; bi = e; }
            used[bi] = true; idx[k] = bi; pv[k] = best; psum += best;
        }
        const float inv = 1.f / psum;
        for (int k = 0; k < KTOP; k++) {
            const int e = idx[k];
            const int pos = atomicAdd(&g_count[e], 1);
            if (pos < CAP) g_tok[e * CAP + pos] = t;
            g_e4[t * KTOP + k] = e;
            g_s4[t * KTOP + k] = pos;
            g_w4[t * KTOP + k] = pv[k] * inv;
        }
    }
}

// ---------------- GEMM layout (fp16 half2 along K) ----------------
// A smem: 128 rows x 16 kp words, stride 20 (LDSM conflict-free).
// B smem: 16 kp x 128 n words, stride 136 (scalar frag LDS conflict-free).
#define ASZ 2560
#define BSZ 2176

// Merged grid decode: bids [0,2048) expert (ez=bid>>6, my=(bid>>3)&7, nx=bid&7);
// bids [2048,2304) shared (my=r>>3, nx=r&7).

// ---------------- gate-up (fp16 mma.sync, fused silu, merged) ----------------
// 128 thr, 4 warps (2M x 2N). block M=128, N=64 gate + 64 up. warp m64.
__global__ void __launch_bounds__(128)
gu_mma(const float* __restrict__ Wge, const float* __restrict__ Wgs) {
    const int bid = blockIdx.x;
    const bool EXP = bid < 2048;
    int ez, my, nx;
    if (EXP) { ez = bid >> 6; my = (bid >> 3) & 7; nx = bid & 7; }
    else     { const int r = bid - 2048; ez = 0; my = r >> 3; nx = r & 7; }
    const int n_e = EXP ? min(g_count[ez], CAP) : TTOK;
    const int m0 = my * 128;
    if (m0 >= n_e) return;
    const int n0 = nx * 64;

    __shared__ uint32_t As_[2 * ASZ];
    __shared__ uint32_t Bs_[2 * BSZ];

    const int tid = threadIdx.x;
    const int wid = tid >> 5, lane = tid & 31;
    const int g = lane >> 2, tig = lane & 3;
    const int wm = wid & 1, wn = wid >> 1;

    const float* W = EXP ? Wge + (size_t)ez * HDIM * (2 * IDIM) : Wgs;
    __half* actb = EXP ? g_act + (size_t)ez * CAP * IDIM : g_shact;

    // A row per thread (invalid rows -> row 0; outputs never stored)
    const __half* arow;
    {
        const int r = m0 + tid;
        arow = g_xh + (size_t)((r < n_e) ? (EXP ? g_tok[ez * CAP + r] : r) : 0) * HDIM;
    }
    const int bk = wid, bq = lane;
    const int bcol = (bq < 16) ? (n0 + bq * 4) : (IDIM + n0 + (bq - 16) * 4);

    float cg[4][4][4], cu[4][4][4];
    #pragma unroll
    for (int a = 0; a < 4; a++)
        #pragma unroll
        for (int b = 0; b < 4; b++)
            #pragma unroll
            for (int d = 0; d < 4; d++) { cg[a][b][d] = 0.f; cu[a][b][d] = 0.f; }

    const uint32_t As_bytes = smem_u32(As_);
    const int lrow = (lane & 7) + ((lane >> 3) & 1) * 8;
    const int lcol = (lane >> 4) * 4;
    const uint32_t a_off = (uint32_t)(((wm * 64 + lrow) * 20 + lcol) * 4);
    const int bbase = tig * 136 + wn * 32 + g;

    uint4 ra16[2];
    float4 rb[4];
    #define GU_LDGA(k0, h) do { \
        ra16[0] = *(const uint4*)(arow + (k0) + (h) * 16); \
        ra16[1] = *(const uint4*)(arow + (k0) + (h) * 16 + 8); \
    } while (0)
    #define GU_LDGB(k0, h) do { \
        _Pragma("unroll") \
        for (int q2 = 0; q2 < 2; q2++) { \
            const int kk = (k0) + 2 * (bk + ((h) * 2 + q2) * 4); \
            rb[q2 * 2 + 0] = *(const float4*)(W + (size_t)kk * (2 * IDIM) + bcol); \
            rb[q2 * 2 + 1] = *(const float4*)(W + (size_t)(kk + 1) * (2 * IDIM) + bcol); \
        } \
    } while (0)
    #define GU_STS(bufi, h) do { \
        *(uint4*)&As_[(bufi) * ASZ + tid * 20 + (h) * 8 + 0] = ra16[0]; \
        *(uint4*)&As_[(bufi) * ASZ + tid * 20 + (h) * 8 + 4] = ra16[1]; \
        _Pragma("unroll") \
        for (int q2 = 0; q2 < 2; q2++) { \
            const int kp = bk + ((h) * 2 + q2) * 4; \
            uint4 u; \
            u.x = pack2(rb[q2 * 2].x, rb[q2 * 2 + 1].x); \
            u.y = pack2(rb[q2 * 2].y, rb[q2 * 2 + 1].y); \
            u.z = pack2(rb[q2 * 2].z, rb[q2 * 2 + 1].z); \
            u.w = pack2(rb[q2 * 2].w, rb[q2 * 2 + 1].w); \
            *(uint4*)&Bs_[(bufi) * BSZ + kp * 136 + bq * 4] = u; \
        } \
    } while (0)
    #define GU_COMP(kf) do { \
        uint32_t a[4][4]; \
        _Pragma("unroll") \
        for (int mf = 0; mf < 4; mf++) \
            ldsm4(a[mf], Aaddr + mf * 1280 + (kf) * 32); \
        _Pragma("unroll") \
        for (int nf = 0; nf < 4; nf++) { \
            const int ob = bbase + (kf) * 1088 + nf * 8; \
            const uint32_t bg0 = Bb[ob],      bg1 = Bb[ob + 544]; \
            const uint32_t bu0 = Bb[ob + 64], bu1 = Bb[ob + 608]; \
            _Pragma("unroll") \
            for (int mf = 0; mf < 4; mf++) { \
                mma16(cg[mf][nf], a[mf], bg0, bg1); \
                mma16(cu[mf][nf], a[mf], bu0, bu1); \
            } \
        } \
    } while (0)

    GU_LDGA(0, 0);  GU_LDGB(0, 0);  GU_STS(0, 0);
    GU_LDGA(0, 1);  GU_LDGB(0, 1);  GU_STS(0, 1);
    __syncthreads();

    const int NC = HDIM / 32;
    for (int c = 0; c < NC; c++) {
        const int buf = c & 1;
        const uint32_t Aaddr = As_bytes + (uint32_t)buf * (ASZ * 4) + a_off;
        const uint32_t* Bb = Bs_ + buf * BSZ;
        const bool more = (c + 1 < NC);
        if (more) { GU_LDGA((c + 1) * 32, 0); GU_LDGB((c + 1) * 32, 0); }
        GU_COMP(0);
        if (more) { GU_STS(buf ^ 1, 0); GU_LDGA((c + 1) * 32, 1); GU_LDGB((c + 1) * 32, 1); }
        GU_COMP(1);
        if (more) { GU_STS(buf ^ 1, 1); }
        __syncthreads();
    }
    #undef GU_LDGA
    #undef GU_LDGB
    #undef GU_STS
    #undef GU_COMP

    // epilogue: silu(gate)*up -> fp16 act
    #pragma unroll
    for (int mf = 0; mf < 4; mf++) {
        #pragma unroll
        for (int nf = 0; nf < 4; nf++) {
            const int row0 = m0 + wm * 64 + mf * 16 + g;
            const int col  = n0 + wn * 32 + nf * 8 + tig * 2;
            if (row0 < n_e) {
                float gv, uv, ox, oy;
                gv = cg[mf][nf][0]; uv = cu[mf][nf][0]; ox = gv / (1.f + __expf(-gv)) * uv;
                gv = cg[mf][nf][1]; uv = cu[mf][nf][1]; oy = gv / (1.f + __expf(-gv)) * uv;
                *(__half2*)(actb + (size_t)row0 * IDIM + col) = __floats2half2_rn(ox, oy);
            }
            if (row0 + 8 < n_e) {
                float gv, uv, ox, oy;
                gv = cg[mf][nf][2]; uv = cu[mf][nf][2]; ox = gv / (1.f + __expf(-gv)) * uv;
                gv = cg[mf][nf][3]; uv = cu[mf][nf][3]; oy = gv / (1.f + __expf(-gv)) * uv;
                *(__half2*)(actb + (size_t)(row0 + 8) * IDIM + col) = __floats2half2_rn(ox, oy);
            }
        }
    }
}

// ---------------- down (fp16 mma.sync, merged) ----------------
// 128 thr, 4 warps (2M x 2N). block M=128 x N=128; warp m64 x n64.
__global__ void __launch_bounds__(128)
dn_mma(const float* __restrict__ Wde, const float* __restrict__ Wds,
       float* __restrict__ out) {
    const int bid = blockIdx.x;
    const bool EXP = bid < 2048;
    int ez, my, nx;
    if (EXP) { ez = bid >> 6; my = (bid >> 3) & 7; nx = bid & 7; }
    else     { const int r = bid - 2048; ez = 0; my = r >> 3; nx = r & 7; }
    const int n_e = EXP ? min(g_count[ez], CAP) : TTOK;
    const int m0 = my * 128;
    if (m0 >= n_e) return;
    const int n0 = nx * 128;

    __shared__ uint32_t As_[2 * ASZ];
    __shared__ uint32_t Bs_[2 * BSZ];

    const int tid = threadIdx.x;
    const int wid = tid >> 5, lane = tid & 31;
    const int g = lane >> 2, tig = lane & 3;
    const int wm = wid & 1, wn = wid >> 1;

    const __half* actb = EXP ? g_act + (size_t)ez * CAP * IDIM : g_shact;
    const float* W = EXP ? Wde + (size_t)ez * IDIM * HDIM : Wds;

    const __half* arow = actb + (size_t)(m0 + tid) * IDIM;
    const int bk = wid, bq = lane;
    const int bcol = n0 + bq * 4;

    float cc[4][8][4];
    #pragma unroll
    for (int a = 0; a < 4; a++)
        #pragma unroll
        for (int b = 0; b < 8; b++)
            #pragma unroll
            for (int d = 0; d < 4; d++) cc[a][b][d] = 0.f;

    const uint32_t As_bytes = smem_u32(As_);
    const int lrow = (lane & 7) + ((lane >> 3) & 1) * 8;
    const int lcol = (lane >> 4) * 4;
    const uint32_t a_off = (uint32_t)(((wm * 64 + lrow) * 20 + lcol) * 4);
    const int bbase = tig * 136 + wn * 64 + g;

    uint4 ra16[2];
    float4 rb[4];
    #define DN_LDGA(k0, h) do { \
        ra16[0] = *(const uint4*)(arow + (k0) + (h) * 16); \
        ra16[1] = *(const uint4*)(arow + (k0) + (h) * 16 + 8); \
    } while (0)
    #define DN_LDGB(k0, h) do { \
        _Pragma("unroll") \
        for (int q2 = 0; q2 < 2; q2++) { \
            const int kk = (k0) + 2 * (bk + ((h) * 2 + q2) * 4); \
            rb[q2 * 2 + 0] = *(const float4*)(W + (size_t)kk * HDIM + bcol); \
            rb[q2 * 2 + 1] = *(const float4*)(W + (size_t)(kk + 1) * HDIM + bcol); \
        } \
    } while (0)
    #define DN_STS(bufi, h) do { \
        *(uint4*)&As_[(bufi) * ASZ + tid * 20 + (h) * 8 + 0] = ra16[0]; \
        *(uint4*)&As_[(bufi) * ASZ + tid * 20 + (h) * 8 + 4] = ra16[1]; \
        _Pragma("unroll") \
        for (int q2 = 0; q2 < 2; q2++) { \
            const int kp = bk + ((h) * 2 + q2) * 4; \
            uint4 u; \
            u.x = pack2(rb[q2 * 2].x, rb[q2 * 2 + 1].x); \
            u.y = pack2(rb[q2 * 2].y, rb[q2 * 2 + 1].y); \
            u.z = pack2(rb[q2 * 2].z, rb[q2 * 2 + 1].z); \
            u.w = pack2(rb[q2 * 2].w, rb[q2 * 2 + 1].w); \
            *(uint4*)&Bs_[(bufi) * BSZ + kp * 136 + bq * 4] = u; \
        } \
    } while (0)
    #define DN_COMP(kf) do { \
        uint32_t a[4][4]; \
        _Pragma("unroll") \
        for (int mf = 0; mf < 4; mf++) \
            ldsm4(a[mf], Aaddr + mf * 1280 + (kf) * 32); \
        _Pragma("unroll") \
        for (int nf = 0; nf < 8; nf++) { \
            const int ob = bbase + (kf) * 1088 + nf * 8; \
            const uint32_t b0 = Bb[ob], b1 = Bb[ob + 544]; \
            _Pragma("unroll") \
            for (int mf = 0; mf < 4; mf++) \
                mma16(cc[mf][nf], a[mf], b0, b1); \
        } \
    } while (0)

    DN_LDGA(0, 0);  DN_LDGB(0, 0);  DN_STS(0, 0);
    DN_LDGA(0, 1);  DN_LDGB(0, 1);  DN_STS(0, 1);
    __syncthreads();

    const int NC = IDIM / 32;
    for (int c = 0; c < NC; c++) {
        const int buf = c & 1;
        const uint32_t Aaddr = As_bytes + (uint32_t)buf * (ASZ * 4) + a_off;
        const uint32_t* Bb = Bs_ + buf * BSZ;
        const bool more = (c + 1 < NC);
        if (more) { DN_LDGA((c + 1) * 32, 0); DN_LDGB((c + 1) * 32, 0); }
        DN_COMP(0);
        if (more) { DN_STS(buf ^ 1, 0); DN_LDGA((c + 1) * 32, 1); DN_LDGB((c + 1) * 32, 1); }
        DN_COMP(1);
        if (more) { DN_STS(buf ^ 1, 1); }
        __syncthreads();
    }
    #undef DN_LDGA
    #undef DN_LDGB
    #undef DN_STS
    #undef DN_COMP

    #pragma unroll
    for (int mf = 0; mf < 4; mf++) {
        #pragma unroll
        for (int nf = 0; nf < 8; nf++) {
            const int row0 = m0 + wm * 64 + mf * 16 + g;
            const int col  = n0 + wn * 64 + nf * 8 + tig * 2;
            if (row0 < n_e) {
                if (EXP) {
                    *(__half2*)(g_dbuf + ((size_t)ez * CAP + row0) * HDIM + col) =
                        __floats2half2_rn(cc[mf][nf][0], cc[mf][nf][1]);
                } else {
                    *(float2*)(out + (size_t)row0 * HDIM + col) =
                        make_float2(cc[mf][nf][0], cc[mf][nf][1]);
                }
            }
            if (row0 + 8 < n_e) {
                if (EXP) {
                    *(__half2*)(g_dbuf + ((size_t)ez * CAP + row0 + 8) * HDIM + col) =
                        __floats2half2_rn(cc[mf][nf][2], cc[mf][nf][3]);
                } else {
                    *(float2*)(out + (size_t)(row0 + 8) * HDIM + col) =
                        make_float2(cc[mf][nf][2], cc[mf][nf][3]);
                }
            }
        }
    }
}

// ---------------- combine ----------------
__global__ void __launch_bounds__(128)
combine_kernel(float* __restrict__ out) {
    const int t = blockIdx.x;
    const int i = threadIdx.x;
    float4* outv = (float4*)out + (size_t)t * 256 + i * 2;
    float4 a0 = outv[0], a1 = outv[1];
    #pragma unroll
    for (int k = 0; k < KTOP; k++) {
        const int e = g_e4[t * KTOP + k];
        const int s = g_s4[t * KTOP + k];
        const float w = g_w4[t * KTOP + k];
        if (s < CAP) {
            const uint4 hv = *(const uint4*)(g_dbuf + ((size_t)e * CAP + s) * HDIM + i * 8);
            const float2 f0 = __half22float2(*(const __half2*)&hv.x);
            const float2 f1 = __half22float2(*(const __half2*)&hv.y);
            const float2 f2 = __half22float2(*(const __half2*)&hv.z);
            const float2 f3 = __half22float2(*(const __half2*)&hv.w);
            a0.x += w * f0.x; a0.y += w * f0.y; a0.z += w * f1.x; a0.w += w * f1.y;
            a1.x += w * f2.x; a1.y += w * f2.y; a1.z += w * f3.x; a1.w += w * f3.y;
        }
    }
    outv[0] = a0; outv[1] = a1;
}

extern "C" void kernel_launch(void* const* d_in, const int* in_sizes, int n_in,
                              void* d_out, int out_size) {
    const float* x   = (const float*)d_in[0];
    const float* gw  = (const float*)d_in[1];
    const float* wgu = (const float*)d_in[2];
    const float* wd  = (const float*)d_in[3];
    const float* sgu = (const float*)d_in[4];
    const float* sd  = (const float*)d_in[5];
    float* out = (float*)d_out;
    (void)in_sizes; (void)n_in; (void)out_size;

    zero_counts_kernel<<<1, 32>>>();
    router_kernel<<<TTOK, 128>>>(x, gw);   // also writes g_xh (fp16 x)

    gu_mma<<<2304, 128>>>(wgu, sgu);
    dn_mma<<<2304, 128>>>(wd, sd, out);

    combine_kernel<<<TTOK, 128>>>(out);
}